// round 12
// baseline (speedup 1.0000x reference)
#include <cuda_runtime.h>
#include <cstdint>

#define MAXN 100000
#define MAXE 2000000

// ---------------- scratch (device globals; no allocation in kernel_launch) ----
__device__ __align__(16) float    g_p[48];                  // p_src[4][6] | p_dst[4][6]
__device__ __align__(16) float    g_as1[MAXN * 4];
__device__ __align__(16) float    g_ad1[MAXN * 4];
__device__ __align__(16) unsigned g_m1[MAXN * 4];           // ordered-uint max
__device__ __align__(16) float    g_acc1[MAXN * 32];        // [n][h][8]: ex0..ex5, denom, pad
__device__ __align__(16) float    g_h1[(size_t)MAXN * 256]; // layer-1 output (post elu)
__device__ __align__(16) float    g_h2[MAXN * 64];          // h1 @ W2
__device__ __align__(16) float    g_as2[MAXN];
__device__ __align__(16) float    g_ad2[MAXN];
__device__ __align__(16) unsigned g_m2[MAXN];
__device__ __align__(16) float    g_acc2[MAXN * 68];        // [n][68]: 64 num, [64]=denom
__device__ __align__(16) float    g_hf[MAXN * 64];          // layer-2 output (post elu)
__device__ __align__(16) int      g_didx[MAXN];
__device__ __align__(16) int      g_src[MAXE];
__device__ __align__(16) int      g_dst[MAXE];
__device__ int g_is64;

// ---------------- helpers ----------------------------------------------------
__device__ __forceinline__ float lrelu(float v) { return v > 0.f ? v : 0.2f * v; }
__device__ __forceinline__ float eluf(float v)  { return v > 0.f ? v : expm1f(v); }
__device__ __forceinline__ unsigned ordf(float f) {
    unsigned u = __float_as_uint(f);
    return (u & 0x80000000u) ? ~u : (u | 0x80000000u);
}
__device__ __forceinline__ float unordf(unsigned u) {
    return __uint_as_float((u & 0x80000000u) ? (u & 0x7fffffffu) : ~u);
}
__device__ __forceinline__ void red4(float* p, float a, float b, float c, float d) {
    asm volatile("red.global.add.v4.f32 [%0], {%1,%2,%3,%4};"
                 :: "l"(__cvta_generic_to_global(p)), "f"(a), "f"(b), "f"(c), "f"(d)
                 : "memory");
}

// ---------------- KD: probe edge_index dtype (int32 vs int64) -----------------
// If data is int32, an int64 view mixes a random node id into the high word ->
// value >= N with overwhelming probability. Reads only the first 128 bytes.
__global__ void kd_detect(const long long* __restrict__ ei, int N) {
    if (threadIdx.x != 0) return;
    bool ok = true;
    #pragma unroll
    for (int i = 0; i < 16; i++) {
        long long v = ei[i];
        if (v < 0 || v >= (long long)N) { ok = false; break; }
    }
    g_is64 = ok ? 1 : 0;
}

// ---------------- KC: decode edge list once into int32 src/dst ----------------
__global__ void kc_cvt(const void* __restrict__ ei, int E, int N) {
    int e = blockIdx.x * blockDim.x + threadIdx.x;
    if (e >= E) return;
    int s, d;
    if (g_is64) {
        const long long* p = (const long long*)ei;
        s = (int)p[e]; d = (int)p[e + E];
    } else {
        const int* p = (const int*)ei;
        s = p[e]; d = p[e + E];
    }
    if ((unsigned)s >= (unsigned)N) s = 0;   // defensive; never expected
    if ((unsigned)d >= (unsigned)N) d = 0;
    g_src[e] = s;
    g_dst[e] = d;
}

// ---------------- K0: p_src/p_dst = W1_h @ att --------------------------------
__global__ void k0_proj(const float* __restrict__ W1,
                        const float* __restrict__ att_s,
                        const float* __restrict__ att_d) {
    int t = threadIdx.x;
    if (t >= 48) return;
    int which = t / 24, r = t % 24, h = r / 6, i = r % 6;
    const float* att = which ? att_d : att_s;
    float s = 0.f;
    #pragma unroll 8
    for (int c = 0; c < 64; c++)
        s += W1[i * 256 + h * 64 + c] * att[h * 64 + c];
    g_p[which * 24 + h * 6 + i] = s;
}

// ---------------- K1: node logits layer 1 + self-loop max init ----------------
__global__ void k1_logits1(const float* __restrict__ x, int N) {
    int n = blockIdx.x * blockDim.x + threadIdx.x;
    if (n >= N) return;
    float xv[6];
    #pragma unroll
    for (int i = 0; i < 6; i++) xv[i] = x[n * 6 + i];
    #pragma unroll
    for (int h = 0; h < 4; h++) {
        float as = 0.f, ad = 0.f;
        #pragma unroll
        for (int i = 0; i < 6; i++) {
            as += xv[i] * g_p[h * 6 + i];
            ad += xv[i] * g_p[24 + h * 6 + i];
        }
        g_as1[n * 4 + h] = as;
        g_ad1[n * 4 + h] = ad;
        g_m1[n * 4 + h]  = ordf(lrelu(as + ad));
    }
}

// ---------------- K2: edge segment-max layer 1 --------------------------------
__global__ void k2_max1(int E) {
    int idx = blockIdx.x * blockDim.x + threadIdx.x;
    if (idx >= E * 4) return;
    int e = idx >> 2, h = idx & 3;
    int s = g_src[e], d = g_dst[e];
    float alpha = lrelu(g_as1[s * 4 + h] + g_ad1[d * 4 + h]);
    atomicMax(&g_m1[d * 4 + h], ordf(alpha));
}

// ---------------- K3: init acc1 with self-loop contribution -------------------
__global__ void k3_init1(const float* __restrict__ x, int N) {
    int idx = blockIdx.x * blockDim.x + threadIdx.x;
    if (idx >= N * 4) return;
    int n = idx >> 2;
    float alpha = lrelu(g_as1[idx] + g_ad1[idx]);
    float e = expf(alpha - unordf(g_m1[idx]));
    float* acc = &g_acc1[idx * 8];
    #pragma unroll
    for (int i = 0; i < 6; i++) acc[i] = e * x[n * 6 + i];
    acc[6] = e;   // denom
    acc[7] = 0.f;
}

// ---------------- K4: edge accumulate layer 1 (8 threads / edge) --------------
__global__ void k4_edge1(const float* __restrict__ x, int E) {
    int idx = blockIdx.x * blockDim.x + threadIdx.x;
    if (idx >= E * 8) return;
    int e = idx >> 3, t = idx & 7;
    int h = t >> 1, hf = t & 1;
    int s = g_src[e], d = g_dst[e];
    float alpha = lrelu(g_as1[s * 4 + h] + g_ad1[d * 4 + h]);
    float ee = expf(alpha - unordf(g_m1[d * 4 + h]));
    const float* xs = x + (size_t)s * 6;
    float a, b, c, w;
    if (hf == 0) { a = xs[0] * ee; b = xs[1] * ee; c = xs[2] * ee; w = xs[3] * ee; }
    else         { a = xs[4] * ee; b = xs[5] * ee; c = ee;         w = 0.f; }
    red4(&g_acc1[((d * 4 + h) << 3) + (hf << 2)], a, b, c, w);
}

// ---------------- K5: out1 = (acc @ W1_h)/denom + b1, elu ---------------------
__global__ void k5_out1(const float* __restrict__ W1,
                        const float* __restrict__ b1, int N) {
    int idx = blockIdx.x * blockDim.x + threadIdx.x;
    if (idx >= N * 256) return;
    int n = idx >> 8, j = idx & 255;
    int h = j >> 6;
    const float* acc = &g_acc1[(n * 4 + h) << 3];
    float inv = 1.f / fmaxf(acc[6], 1e-16f);
    float v = 0.f;
    #pragma unroll
    for (int i = 0; i < 6; i++) v += acc[i] * W1[i * 256 + j];
    v = v * inv + b1[j];
    g_h1[(size_t)idx] = eluf(v);
}

// ---------------- K6: h2 = h1 @ W2  (16 nodes/block, reg-tiled) ---------------
__global__ void k6_gemm(const float* __restrict__ W2, int N) {
    __shared__ __align__(16) float sh[256 * 20];  // transposed, padded to 20
    int base = blockIdx.x * 16;
    int t = threadIdx.x;
    for (int idx = t; idx < 16 * 256; idx += 256) {
        int node = idx >> 8, k = idx & 255;
        int n = base + node;
        sh[k * 20 + node] = (n < N) ? g_h1[(size_t)n * 256 + k] : 0.f;
    }
    __syncthreads();
    int j = t & 63, ng = t >> 6;
    float a0 = 0.f, a1 = 0.f, a2 = 0.f, a3 = 0.f;
    const float* wp = W2 + j;
    #pragma unroll 4
    for (int k = 0; k < 256; k++) {
        float4 h = *(const float4*)&sh[k * 20 + ng * 4];
        float w = wp[k * 64];
        a0 += h.x * w; a1 += h.y * w; a2 += h.z * w; a3 += h.w * w;
    }
    int n0 = base + ng * 4;
    if (n0 + 0 < N) g_h2[(n0 + 0) * 64 + j] = a0;
    if (n0 + 1 < N) g_h2[(n0 + 1) * 64 + j] = a1;
    if (n0 + 2 < N) g_h2[(n0 + 2) * 64 + j] = a2;
    if (n0 + 3 < N) g_h2[(n0 + 3) * 64 + j] = a3;
}

// ---------------- K6b: layer-2 logits (warp per node) -------------------------
__global__ void k6b_logits2(const float* __restrict__ att_s,
                            const float* __restrict__ att_d, int N) {
    int gt = blockIdx.x * blockDim.x + threadIdx.x;
    int n = gt >> 5, l = gt & 31;
    if (n >= N) return;
    float h0 = g_h2[n * 64 + l], h1v = g_h2[n * 64 + l + 32];
    float s = h0 * att_s[l] + h1v * att_s[l + 32];
    float d = h0 * att_d[l] + h1v * att_d[l + 32];
    #pragma unroll
    for (int o = 16; o; o >>= 1) {
        s += __shfl_down_sync(0xffffffffu, s, o);
        d += __shfl_down_sync(0xffffffffu, d, o);
    }
    if (l == 0) {
        g_as2[n] = s;
        g_ad2[n] = d;
        g_m2[n]  = ordf(lrelu(s + d));
    }
}

// ---------------- K7: edge segment-max layer 2 --------------------------------
__global__ void k7_max2(int E) {
    int e = blockIdx.x * blockDim.x + threadIdx.x;
    if (e >= E) return;
    int s = g_src[e], d = g_dst[e];
    float alpha = lrelu(g_as2[s] + g_ad2[d]);
    atomicMax(&g_m2[d], ordf(alpha));
}

// ---------------- K8: init acc2 with self-loop --------------------------------
__global__ void k8_init2(int N) {
    int idx = blockIdx.x * blockDim.x + threadIdx.x;
    if (idx >= N * 65) return;
    int n = idx / 65, j = idx - n * 65;
    float alpha = lrelu(g_as2[n] + g_ad2[n]);
    float e = expf(alpha - unordf(g_m2[n]));
    if (j < 64) g_acc2[n * 68 + j] = e * g_h2[n * 64 + j];
    else        g_acc2[n * 68 + 64] = e;
}

// ---------------- K9: edge accumulate layer 2 (16 threads / edge) -------------
__global__ void k9_edge2(int E) {
    int idx = blockIdx.x * blockDim.x + threadIdx.x;
    if (idx >= E * 16) return;
    int e = idx >> 4, t = idx & 15;
    int s = g_src[e], d = g_dst[e];
    float alpha = lrelu(g_as2[s] + g_ad2[d]);
    float ee = expf(alpha - unordf(g_m2[d]));
    float4 h = *(const float4*)&g_h2[s * 64 + t * 4];
    red4(&g_acc2[d * 68 + t * 4], h.x * ee, h.y * ee, h.z * ee, h.w * ee);
    if (t == 0) atomicAdd(&g_acc2[d * 68 + 64], ee);
}

// ---------------- K10: final layer-2 output -----------------------------------
__global__ void k10_out2(const float* __restrict__ b2, int N) {
    int idx = blockIdx.x * blockDim.x + threadIdx.x;
    if (idx >= N * 64) return;
    int n = idx >> 6, j = idx & 63;
    float denom = g_acc2[n * 68 + 64];
    float v = g_acc2[n * 68 + j] / fmaxf(denom, 1e-16f) + b2[j];
    g_hf[idx] = eluf(v);
}

// ---------------- K11: stable compaction of drone indices ---------------------
__global__ void k11_compact(const float* __restrict__ x, int N, int nd) {
    __shared__ int swt[32];
    __shared__ int sws[32];
    __shared__ int soff;
    int t = threadIdx.x, w = t >> 5, l = t & 31;
    for (int i = t; i < nd; i += 1024) g_didx[i] = 0;
    if (t == 0) soff = 0;
    __syncthreads();
    for (int base = 0; base < N; base += 1024) {
        int n = base + t;
        int flag = (n < N) && (x[n * 6 + 5] == 1.0f);
        unsigned m = __ballot_sync(0xffffffffu, flag);
        int wpre = __popc(m & ((1u << l) - 1u));
        if (l == 0) swt[w] = __popc(m);
        __syncthreads();
        if (w == 0) {
            int v = swt[l];
            #pragma unroll
            for (int off = 1; off < 32; off <<= 1) {
                int u = __shfl_up_sync(0xffffffffu, v, off);
                if (l >= off) v += u;
            }
            sws[l] = v;
        }
        __syncthreads();
        int wbase = soff + (w ? sws[w - 1] : 0);
        if (flag) {
            int pos = wbase + wpre;
            if (pos < nd) g_didx[pos] = n;
        }
        __syncthreads();
        if (t == 0) soff += sws[31];
        __syncthreads();
    }
}

// ---------------- K12: drone MLP head -----------------------------------------
__global__ void k12_mlp(const float* __restrict__ fc1w, const float* __restrict__ fc1b,
                        const float* __restrict__ fc2w, const float* __restrict__ fc2b,
                        float* __restrict__ out, int nd) {
    __shared__ float sh[64];
    __shared__ float sz[64];
    int b = blockIdx.x;
    if (b >= nd) return;
    int n = g_didx[b];
    int j = threadIdx.x;
    sh[j] = g_hf[n * 64 + j];
    __syncthreads();
    float v = fc1b[j];
    #pragma unroll 8
    for (int k = 0; k < 64; k++) v += sh[k] * fc1w[k * 64 + j];
    sz[j] = fmaxf(v, 0.f);
    __syncthreads();
    if (j < 2) {
        float o = fc2b[j];
        #pragma unroll 8
        for (int k = 0; k < 64; k++) o += sz[k] * fc2w[k * 2 + j];
        out[b * 2 + j] = 2.f * tanhf(o);
    }
}

// ---------------- launch ------------------------------------------------------
static inline int cdiv(long long a, int b) { return (int)((a + b - 1) / b); }

extern "C" void kernel_launch(void* const* d_in, const int* in_sizes, int n_in,
                              void* d_out, int out_size) {
    // ---- Robust size-based input identification (element counts) ----
    // edge_index=2E (largest), x=6N (2nd largest), W2=16384, fc1_w=4096,
    // W1=1536, fc2_w=128, fc2_b=2, n_drones=1.
    // 256-group {att_src1, att_dst1, b1}: b1 last. 64-group {att_src2,
    // att_dst2, b2, fc1_b}: b2 third, fc1_b fourth. src/dst order within
    // groups flips if global ordering is alphabetical (edge_index not slot 1).
    const void* p_ei = nullptr; const float* x = nullptr;
    const float *W1 = 0, *W2 = 0, *fc1w = 0, *fc2w = 0, *fc2b = 0;
    const float* s256[3] = {0, 0, 0}; int n256 = 0;
    const float* s64g[4] = {0, 0, 0, 0}; int n64 = 0;
    long long sz_big1 = 0, sz_big2 = 0;
    const void *p_big1 = 0, *p_big2 = 0;

    for (int i = 0; i < n_in; i++) {
        long long s = in_sizes[i];
        const void* p = d_in[i];
        if (s > 20000) {
            if (s > sz_big1) { sz_big2 = sz_big1; p_big2 = p_big1; sz_big1 = s; p_big1 = p; }
            else if (s > sz_big2) { sz_big2 = s; p_big2 = p; }
        } else if (s == 16384) W2 = (const float*)p;
        else if (s == 4096) fc1w = (const float*)p;
        else if (s == 1536) W1 = (const float*)p;
        else if (s == 128)  fc2w = (const float*)p;
        else if (s == 2)    fc2b = (const float*)p;
        else if (s == 256) { if (n256 < 3) s256[n256++] = (const float*)p; }
        else if (s == 64)  { if (n64 < 4)  s64g[n64++] = (const float*)p; }
        // s == 1 -> n_drones scalar (derived from out_size instead)
    }
    p_ei = p_big1;                      // 2E elements (dtype probed on device)
    x    = (const float*)p_big2;        // 6N elements

    bool insertion = (n_in >= 2) && ((long long)in_sizes[1] == sz_big1);
    const float* a_s1 = insertion ? s256[0] : s256[1];
    const float* a_d1 = insertion ? s256[1] : s256[0];
    const float* b1   = s256[2];
    const float* a_s2 = insertion ? s64g[0] : s64g[1];
    const float* a_d2 = insertion ? s64g[1] : s64g[0];
    const float* b2   = s64g[2];
    const float* fc1b = s64g[3];
    float* out = (float*)d_out;

    int N  = (int)(sz_big2 / 6);
    int E  = (int)(sz_big1 / 2);
    int nd = out_size / 2;
    if (N > MAXN) N = MAXN;
    if (E > MAXE) E = MAXE;

    kd_detect  <<<1, 32>>>((const long long*)p_ei, N);
    kc_cvt     <<<cdiv(E, 256), 256>>>(p_ei, E, N);
    k0_proj    <<<1, 64>>>(W1, a_s1, a_d1);
    k1_logits1 <<<cdiv(N, 256), 256>>>(x, N);
    k2_max1    <<<cdiv((long long)E * 4, 256), 256>>>(E);
    k3_init1   <<<cdiv((long long)N * 4, 256), 256>>>(x, N);
    k4_edge1   <<<cdiv((long long)E * 8, 256), 256>>>(x, E);
    k5_out1    <<<cdiv((long long)N * 256, 256), 256>>>(W1, b1, N);
    k6_gemm    <<<cdiv(N, 16), 256>>>(W2, N);
    k6b_logits2<<<cdiv((long long)N * 32, 256), 256>>>(a_s2, a_d2, N);
    k7_max2    <<<cdiv(E, 256), 256>>>(E);
    k8_init2   <<<cdiv((long long)N * 65, 256), 256>>>(N);
    k9_edge2   <<<cdiv((long long)E * 16, 256), 256>>>(E);
    k10_out2   <<<cdiv((long long)N * 64, 256), 256>>>(b2, N);
    k11_compact<<<1, 1024>>>(x, N, nd);
    k12_mlp    <<<nd, 64>>>(fc1w, fc1b, fc2w, fc2b, out, nd);
}

// round 13
// speedup vs baseline: 1.4983x; 1.4983x over previous
#include <cuda_runtime.h>
#include <cstdint>

#define MAXN 100000
#define MAXE 2000000
#define MAXNB 128   // max 1024-blocks covering N

// ---------------- scratch (device globals) ------------------------------------
__device__ __align__(16) float g_p[48];                    // p_src[4][6] | p_dst[4][6]
__device__ __align__(16) float g_as1[MAXN * 4];
__device__ __align__(16) float g_ad1[MAXN * 4];
__device__ __align__(16) float g_acc1[MAXN * 32];          // [n][h][8]: sum(e*x0..5), denom
__device__ __align__(16) float g_h1[(size_t)MAXN * 256];   // layer-1 output (post elu)
__device__ __align__(16) float g_h2[MAXN * 64];            // h1 @ W2
__device__ __align__(16) float g_as2[MAXN];
__device__ __align__(16) float g_ad2[MAXN];
__device__ __align__(16) float g_hf[MAXN * 64];            // layer-2 output (post elu)
__device__ __align__(16) int   g_didx[MAXN];
__device__ __align__(16) int   g_src[MAXE];
__device__ __align__(16) int   g_dst[MAXE];
__device__ __align__(16) int   g_csr[MAXE];                // src ids grouped by dst
__device__ __align__(16) int   g_deg[MAXN];
__device__ __align__(16) int   g_off[MAXN];
__device__ __align__(16) int   g_wr[MAXN];
__device__ int g_bsum[MAXNB];
__device__ int g_boff[MAXNB];
__device__ int g_dsum[MAXNB];
__device__ int g_dboff[MAXNB];
__device__ int g_is64;

// ---------------- helpers ----------------------------------------------------
__device__ __forceinline__ float lrelu(float v) { return v > 0.f ? v : 0.2f * v; }
__device__ __forceinline__ float eluf(float v)  { return v > 0.f ? v : expm1f(v); }

// ---------------- KD: probe edge_index dtype (int32 vs int64) -----------------
__global__ void kd_detect(const long long* __restrict__ ei, int N) {
    if (threadIdx.x != 0) return;
    bool ok = true;
    #pragma unroll
    for (int i = 0; i < 16; i++) {
        long long v = ei[i];
        if (v < 0 || v >= (long long)N) { ok = false; break; }
    }
    g_is64 = ok ? 1 : 0;
}

// ---------------- KZ: zero deg + didx -----------------------------------------
__global__ void kz_zero(int N) {
    int n = blockIdx.x * blockDim.x + threadIdx.x;
    if (n < N) { g_deg[n] = 0; g_didx[n] = 0; }
}

// ---------------- KC: decode edge list + histogram ----------------------------
__global__ void kc_cvt(const void* __restrict__ ei, int E, int N) {
    int e = blockIdx.x * blockDim.x + threadIdx.x;
    if (e >= E) return;
    int s, d;
    if (g_is64) {
        const long long* p = (const long long*)ei;
        s = (int)p[e]; d = (int)p[e + E];
    } else {
        const int* p = (const int*)ei;
        s = p[e]; d = p[e + E];
    }
    if ((unsigned)s >= (unsigned)N) s = 0;
    if ((unsigned)d >= (unsigned)N) d = 0;
    g_src[e] = s;
    g_dst[e] = d;
    atomicAdd(&g_deg[d], 1);
}

// ---------------- KS1: per-block degree sums ----------------------------------
__global__ void ks1_bsum(int N) {
    int b = blockIdx.x, t = threadIdx.x, n = b * 1024 + t;
    int v = (n < N) ? g_deg[n] : 0;
    int l = t & 31, w = t >> 5;
    #pragma unroll
    for (int o = 16; o; o >>= 1) v += __shfl_down_sync(0xffffffffu, v, o);
    __shared__ int ws[32];
    if (l == 0) ws[w] = v;
    __syncthreads();
    if (w == 0) {
        int s = ws[l];
        #pragma unroll
        for (int o = 16; o; o >>= 1) s += __shfl_down_sync(0xffffffffu, s, o);
        if (l == 0) g_bsum[b] = s;
    }
}

// ---------------- KS2: exclusive scan of block sums (<=128 values) ------------
__global__ void ks2_bscan(int nb) {
    int t = threadIdx.x;  // blockDim = 128
    __shared__ int sh[128];
    int v = (t < nb) ? g_bsum[t] : 0;
    sh[t] = v;
    __syncthreads();
    for (int o = 1; o < 128; o <<= 1) {
        int u = (t >= o) ? sh[t - o] : 0;
        __syncthreads();
        sh[t] += u;
        __syncthreads();
    }
    if (t < nb) g_boff[t] = sh[t] - v;
}

// ---------------- KS3: per-node exclusive offsets -----------------------------
__global__ void ks3_scan(int N) {
    int b = blockIdx.x, t = threadIdx.x, n = b * 1024 + t;
    int l = t & 31, w = t >> 5;
    int v = (n < N) ? g_deg[n] : 0;
    int s = v;
    #pragma unroll
    for (int o = 1; o < 32; o <<= 1) {
        int u = __shfl_up_sync(0xffffffffu, s, o);
        if (l >= o) s += u;
    }
    __shared__ int ws[32];
    if (l == 31) ws[w] = s;
    __syncthreads();
    if (w == 0) {
        int x2 = ws[l];
        #pragma unroll
        for (int o = 1; o < 32; o <<= 1) {
            int u = __shfl_up_sync(0xffffffffu, x2, o);
            if (l >= o) x2 += u;
        }
        ws[l] = x2;
    }
    __syncthreads();
    int excl = s - v + (w ? ws[w - 1] : 0) + g_boff[b];
    if (n < N) { g_off[n] = excl; g_wr[n] = excl; }
}

// ---------------- KSC: scatter srcs into CSR ----------------------------------
__global__ void kscat(int E) {
    int e = blockIdx.x * blockDim.x + threadIdx.x;
    if (e >= E) return;
    int d = g_dst[e];
    int pos = atomicAdd(&g_wr[d], 1);
    g_csr[pos] = g_src[e];
}

// ---------------- K0: p_src/p_dst = W1_h @ att --------------------------------
__global__ void k0_proj(const float* __restrict__ W1,
                        const float* __restrict__ att_s,
                        const float* __restrict__ att_d) {
    int t = threadIdx.x;
    if (t >= 48) return;
    int which = t / 24, r = t % 24, h = r / 6, i = r % 6;
    const float* att = which ? att_d : att_s;
    float s = 0.f;
    #pragma unroll 8
    for (int c = 0; c < 64; c++)
        s += W1[i * 256 + h * 64 + c] * att[h * 64 + c];
    g_p[which * 24 + h * 6 + i] = s;
}

// ---------------- K1: node logits layer 1 -------------------------------------
__global__ void k1_logits1(const float* __restrict__ x, int N) {
    int n = blockIdx.x * blockDim.x + threadIdx.x;
    if (n >= N) return;
    float xv[6];
    #pragma unroll
    for (int i = 0; i < 6; i++) xv[i] = x[n * 6 + i];
    #pragma unroll
    for (int h = 0; h < 4; h++) {
        float as = 0.f, ad = 0.f;
        #pragma unroll
        for (int i = 0; i < 6; i++) {
            as += xv[i] * g_p[h * 6 + i];
            ad += xv[i] * g_p[24 + h * 6 + i];
        }
        g_as1[n * 4 + h] = as;
        g_ad1[n * 4 + h] = ad;
    }
}

// ---------------- K4: layer-1 CSR aggregation (thread per dst×head) -----------
// exp without max-shift: mathematically identical softmax, values bounded.
__global__ void k4_csr(const float* __restrict__ x, int N) {
    int idx = blockIdx.x * blockDim.x + threadIdx.x;
    if (idx >= N * 4) return;
    int d = idx >> 2;
    float adh = g_ad1[idx];
    int off = g_off[d], deg = g_deg[d];
    // self-loop first
    float a0, a1, a2, a3, a4, a5, den;
    {
        float ee = __expf(lrelu(g_as1[idx] + adh));
        const float2* xp = (const float2*)(x + (size_t)d * 6);
        float2 x0 = xp[0], x1 = xp[1], x2 = xp[2];
        a0 = ee * x0.x; a1 = ee * x0.y; a2 = ee * x1.x;
        a3 = ee * x1.y; a4 = ee * x2.x; a5 = ee * x2.y;
        den = ee;
    }
    for (int i = 0; i < deg; i++) {
        int s = g_csr[off + i];
        float ee = __expf(lrelu(g_as1[s * 4 + (idx & 3)] + adh));
        const float2* xp = (const float2*)(x + (size_t)s * 6);
        float2 x0 = xp[0], x1 = xp[1], x2 = xp[2];
        a0 += ee * x0.x; a1 += ee * x0.y; a2 += ee * x1.x;
        a3 += ee * x1.y; a4 += ee * x2.x; a5 += ee * x2.y;
        den += ee;
    }
    float* acc = &g_acc1[idx * 8];
    acc[0] = a0; acc[1] = a1; acc[2] = a2;
    acc[3] = a3; acc[4] = a4; acc[5] = a5;
    acc[6] = den;
}

// ---------------- K5: out1 = (acc @ W1_h)/denom + b1, elu ---------------------
__global__ void k5_out1(const float* __restrict__ W1,
                        const float* __restrict__ b1, int N) {
    int idx = blockIdx.x * blockDim.x + threadIdx.x;
    if (idx >= N * 256) return;
    int n = idx >> 8, j = idx & 255;
    int h = j >> 6;
    const float* acc = &g_acc1[(n * 4 + h) << 3];
    float inv = 1.f / fmaxf(acc[6], 1e-16f);
    float v = 0.f;
    #pragma unroll
    for (int i = 0; i < 6; i++) v += acc[i] * W1[i * 256 + j];
    v = v * inv + b1[j];
    g_h1[(size_t)idx] = eluf(v);
}

// ---------------- K6: h2 = h1 @ W2  (16 nodes/block, reg-tiled) ---------------
__global__ void k6_gemm(const float* __restrict__ W2, int N) {
    __shared__ __align__(16) float sh[256 * 20];
    int base = blockIdx.x * 16;
    int t = threadIdx.x;
    for (int idx = t; idx < 16 * 256; idx += 256) {
        int node = idx >> 8, k = idx & 255;
        int n = base + node;
        sh[k * 20 + node] = (n < N) ? g_h1[(size_t)n * 256 + k] : 0.f;
    }
    __syncthreads();
    int j = t & 63, ng = t >> 6;
    float a0 = 0.f, a1 = 0.f, a2 = 0.f, a3 = 0.f;
    const float* wp = W2 + j;
    #pragma unroll 4
    for (int k = 0; k < 256; k++) {
        float4 h = *(const float4*)&sh[k * 20 + ng * 4];
        float w = wp[k * 64];
        a0 += h.x * w; a1 += h.y * w; a2 += h.z * w; a3 += h.w * w;
    }
    int n0 = base + ng * 4;
    if (n0 + 0 < N) g_h2[(n0 + 0) * 64 + j] = a0;
    if (n0 + 1 < N) g_h2[(n0 + 1) * 64 + j] = a1;
    if (n0 + 2 < N) g_h2[(n0 + 2) * 64 + j] = a2;
    if (n0 + 3 < N) g_h2[(n0 + 3) * 64 + j] = a3;
}

// ---------------- K6b: layer-2 logits (warp per node) -------------------------
__global__ void k6b_logits2(const float* __restrict__ att_s,
                            const float* __restrict__ att_d, int N) {
    int gt = blockIdx.x * blockDim.x + threadIdx.x;
    int n = gt >> 5, l = gt & 31;
    if (n >= N) return;
    float h0 = g_h2[n * 64 + l], h1v = g_h2[n * 64 + l + 32];
    float s = h0 * att_s[l] + h1v * att_s[l + 32];
    float d = h0 * att_d[l] + h1v * att_d[l + 32];
    #pragma unroll
    for (int o = 16; o; o >>= 1) {
        s += __shfl_down_sync(0xffffffffu, s, o);
        d += __shfl_down_sync(0xffffffffu, d, o);
    }
    if (l == 0) { g_as2[n] = s; g_ad2[n] = d; }
}

// ---------------- K9: layer-2 CSR aggregation, fully fused --------------------
// warp per dst; float2 per lane; self-loop + softmax denom + bias + elu fused.
__global__ void k9_csr(const float* __restrict__ b2, int N) {
    int gt = blockIdx.x * blockDim.x + threadIdx.x;
    int d = gt >> 5, l = gt & 31;
    if (d >= N) return;
    float add = g_ad2[d];
    int off = g_off[d], deg = g_deg[d];
    float eeS = __expf(lrelu(g_as2[d] + add));
    float2 hd = *(const float2*)&g_h2[d * 64 + l * 2];
    float ax = eeS * hd.x, ay = eeS * hd.y, den = eeS;
    int i = 0;
    for (; i + 2 <= deg; i += 2) {
        int s0 = g_csr[off + i], s1 = g_csr[off + i + 1];
        float as0 = g_as2[s0], as1v = g_as2[s1];
        float2 h0 = *(const float2*)&g_h2[s0 * 64 + l * 2];
        float2 h1 = *(const float2*)&g_h2[s1 * 64 + l * 2];
        float e0 = __expf(lrelu(as0 + add));
        float e1 = __expf(lrelu(as1v + add));
        ax += e0 * h0.x + e1 * h1.x;
        ay += e0 * h0.y + e1 * h1.y;
        den += e0 + e1;
    }
    if (i < deg) {
        int s0 = g_csr[off + i];
        float e0 = __expf(lrelu(g_as2[s0] + add));
        float2 h0 = *(const float2*)&g_h2[s0 * 64 + l * 2];
        ax += e0 * h0.x; ay += e0 * h0.y; den += e0;
    }
    float inv = 1.f / fmaxf(den, 1e-16f);
    float v0 = ax * inv + b2[l * 2];
    float v1 = ay * inv + b2[l * 2 + 1];
    *(float2*)&g_hf[d * 64 + l * 2] = make_float2(eluf(v0), eluf(v1));
}

// ---------------- KCA/KCB/KCC: multi-block stable drone compaction ------------
__global__ void kca_count(const float* __restrict__ x, int N) {
    int b = blockIdx.x, t = threadIdx.x, n = b * 1024 + t;
    int l = t & 31, w = t >> 5;
    int f = (n < N) && (x[n * 6 + 5] == 1.0f);
    unsigned m = __ballot_sync(0xffffffffu, f);
    __shared__ int ws[32];
    if (l == 0) ws[w] = __popc(m);
    __syncthreads();
    if (w == 0) {
        int s = ws[l];
        #pragma unroll
        for (int o = 16; o; o >>= 1) s += __shfl_down_sync(0xffffffffu, s, o);
        if (l == 0) g_dsum[b] = s;
    }
}
__global__ void kcb_scan(int nb) {
    int t = threadIdx.x;  // 128
    __shared__ int sh[128];
    int v = (t < nb) ? g_dsum[t] : 0;
    sh[t] = v;
    __syncthreads();
    for (int o = 1; o < 128; o <<= 1) {
        int u = (t >= o) ? sh[t - o] : 0;
        __syncthreads();
        sh[t] += u;
        __syncthreads();
    }
    if (t < nb) g_dboff[t] = sh[t] - v;
}
__global__ void kcc_scatter(const float* __restrict__ x, int N, int nd) {
    int b = blockIdx.x, t = threadIdx.x, n = b * 1024 + t;
    int l = t & 31, w = t >> 5;
    int f = (n < N) && (x[n * 6 + 5] == 1.0f);
    unsigned m = __ballot_sync(0xffffffffu, f);
    int wpre = __popc(m & ((1u << l) - 1u));
    __shared__ int ws[32];
    if (l == 0) ws[w] = __popc(m);
    __syncthreads();
    if (w == 0) {
        int v = ws[l];
        #pragma unroll
        for (int o = 1; o < 32; o <<= 1) {
            int u = __shfl_up_sync(0xffffffffu, v, o);
            if (l >= o) v += u;
        }
        ws[l] = v;
    }
    __syncthreads();
    int base = g_dboff[b] + (w ? ws[w - 1] : 0);
    if (f) {
        int pos = base + wpre;
        if (pos < nd) g_didx[pos] = n;
    }
}

// ---------------- K12: drone MLP head -----------------------------------------
__global__ void k12_mlp(const float* __restrict__ fc1w, const float* __restrict__ fc1b,
                        const float* __restrict__ fc2w, const float* __restrict__ fc2b,
                        float* __restrict__ out, int nd) {
    __shared__ float sh[64];
    __shared__ float sz[64];
    int b = blockIdx.x;
    if (b >= nd) return;
    int n = g_didx[b];
    int j = threadIdx.x;
    sh[j] = g_hf[n * 64 + j];
    __syncthreads();
    float v = fc1b[j];
    #pragma unroll 8
    for (int k = 0; k < 64; k++) v += sh[k] * fc1w[k * 64 + j];
    sz[j] = fmaxf(v, 0.f);
    __syncthreads();
    if (j < 2) {
        float o = fc2b[j];
        #pragma unroll 8
        for (int k = 0; k < 64; k++) o += sz[k] * fc2w[k * 2 + j];
        out[b * 2 + j] = 2.f * tanhf(o);
    }
}

// ---------------- launch ------------------------------------------------------
static inline int cdiv(long long a, int b) { return (int)((a + b - 1) / b); }

extern "C" void kernel_launch(void* const* d_in, const int* in_sizes, int n_in,
                              void* d_out, int out_size) {
    // ---- size-based input identification (element counts) ----
    const void* p_ei = nullptr; const float* x = nullptr;
    const float *W1 = 0, *W2 = 0, *fc1w = 0, *fc2w = 0, *fc2b = 0;
    const float* s256[3] = {0, 0, 0}; int n256 = 0;
    const float* s64g[4] = {0, 0, 0, 0}; int n64 = 0;
    long long sz_big1 = 0, sz_big2 = 0;
    const void *p_big1 = 0, *p_big2 = 0;

    for (int i = 0; i < n_in; i++) {
        long long s = in_sizes[i];
        const void* p = d_in[i];
        if (s > 20000) {
            if (s > sz_big1) { sz_big2 = sz_big1; p_big2 = p_big1; sz_big1 = s; p_big1 = p; }
            else if (s > sz_big2) { sz_big2 = s; p_big2 = p; }
        } else if (s == 16384) W2 = (const float*)p;
        else if (s == 4096) fc1w = (const float*)p;
        else if (s == 1536) W1 = (const float*)p;
        else if (s == 128)  fc2w = (const float*)p;
        else if (s == 2)    fc2b = (const float*)p;
        else if (s == 256) { if (n256 < 3) s256[n256++] = (const float*)p; }
        else if (s == 64)  { if (n64 < 4)  s64g[n64++] = (const float*)p; }
    }
    p_ei = p_big1;
    x    = (const float*)p_big2;

    bool insertion = (n_in >= 2) && ((long long)in_sizes[1] == sz_big1);
    const float* a_s1 = insertion ? s256[0] : s256[1];
    const float* a_d1 = insertion ? s256[1] : s256[0];
    const float* b1   = s256[2];
    const float* a_s2 = insertion ? s64g[0] : s64g[1];
    const float* a_d2 = insertion ? s64g[1] : s64g[0];
    const float* b2   = s64g[2];
    const float* fc1b = s64g[3];
    float* out = (float*)d_out;

    int N  = (int)(sz_big2 / 6);
    int E  = (int)(sz_big1 / 2);
    int nd = out_size / 2;
    if (N > MAXN) N = MAXN;
    if (E > MAXE) E = MAXE;
    int nb = cdiv(N, 1024);            // <= 98

    kd_detect  <<<1, 32>>>((const long long*)p_ei, N);
    kz_zero    <<<nb, 1024>>>(N);
    kc_cvt     <<<cdiv(E, 256), 256>>>(p_ei, E, N);
    ks1_bsum   <<<nb, 1024>>>(N);
    ks2_bscan  <<<1, 128>>>(nb);
    ks3_scan   <<<nb, 1024>>>(N);
    kscat      <<<cdiv(E, 256), 256>>>(E);
    k0_proj    <<<1, 64>>>(W1, a_s1, a_d1);
    k1_logits1 <<<cdiv(N, 256), 256>>>(x, N);
    k4_csr     <<<cdiv((long long)N * 4, 256), 256>>>(x, N);
    k5_out1    <<<cdiv((long long)N * 256, 256), 256>>>(W1, b1, N);
    k6_gemm    <<<cdiv(N, 16), 256>>>(W2, N);
    k6b_logits2<<<cdiv((long long)N * 32, 256), 256>>>(a_s2, a_d2, N);
    k9_csr     <<<cdiv((long long)N * 32, 256), 256>>>(b2, N);
    kca_count  <<<nb, 1024>>>(x, N);
    kcb_scan   <<<1, 128>>>(nb);
    kcc_scatter<<<nb, 1024>>>(x, N, nd);
    k12_mlp    <<<nd, 64>>>(fc1w, fc1b, fc2w, fc2b, out, nd);
}

// round 14
// speedup vs baseline: 1.8851x; 1.2582x over previous
#include <cuda_runtime.h>
#include <cstdint>

#define MAXN 100000
#define MAXE 2000000
#define MAXNB 128   // max 1024-blocks covering N

// ---------------- scratch (device globals) ------------------------------------
__device__ __align__(16) float g_p[48];                    // p_src[4][6] | p_dst[4][6]
__device__ __align__(16) float g_as1[MAXN * 4];
__device__ __align__(16) float g_ad1[MAXN * 4];
__device__ __align__(16) float g_acc1[MAXN * 32];          // [n][h][8]: sum(e*x0..5), den, pad
__device__ __align__(16) float g_h2[MAXN * 64];            // elu(out1) @ W2
__device__ __align__(16) float g_as2[MAXN];
__device__ __align__(16) float g_ad2[MAXN];
__device__ __align__(16) float g_hf[MAXN * 64];            // layer-2 output (post elu)
__device__ __align__(16) int   g_didx[MAXN];
__device__ __align__(16) int   g_src[MAXE];
__device__ __align__(16) int   g_dst[MAXE];
__device__ __align__(16) int   g_csr[MAXE];                // src ids grouped by dst
__device__ __align__(16) int   g_deg[MAXN];
__device__ __align__(16) int   g_off[MAXN];
__device__ __align__(16) int   g_wr[MAXN];
__device__ int g_bsum[MAXNB];
__device__ int g_boff[MAXNB];
__device__ int g_dsum[MAXNB];
__device__ int g_dboff[MAXNB];
__device__ int g_is64;

// ---------------- helpers ----------------------------------------------------
__device__ __forceinline__ float lrelu(float v) { return v > 0.f ? v : 0.2f * v; }
__device__ __forceinline__ float eluf(float v)  { return v > 0.f ? v : expm1f(v); }

// ---------------- KD: probe edge_index dtype (int32 vs int64) -----------------
__global__ void kd_detect(const long long* __restrict__ ei, int N) {
    if (threadIdx.x != 0) return;
    bool ok = true;
    #pragma unroll
    for (int i = 0; i < 16; i++) {
        long long v = ei[i];
        if (v < 0 || v >= (long long)N) { ok = false; break; }
    }
    g_is64 = ok ? 1 : 0;
}

// ---------------- KZ: zero deg + didx -----------------------------------------
__global__ void kz_zero(int N) {
    int n = blockIdx.x * blockDim.x + threadIdx.x;
    if (n < N) { g_deg[n] = 0; g_didx[n] = 0; }
}

// ---------------- KC: decode edge list + histogram ----------------------------
__global__ void kc_cvt(const void* __restrict__ ei, int E, int N) {
    int e = blockIdx.x * blockDim.x + threadIdx.x;
    if (e >= E) return;
    int s, d;
    if (g_is64) {
        const long long* p = (const long long*)ei;
        s = (int)p[e]; d = (int)p[e + E];
    } else {
        const int* p = (const int*)ei;
        s = p[e]; d = p[e + E];
    }
    if ((unsigned)s >= (unsigned)N) s = 0;
    if ((unsigned)d >= (unsigned)N) d = 0;
    g_src[e] = s;
    g_dst[e] = d;
    atomicAdd(&g_deg[d], 1);
}

// ---------------- KS1: per-block degree sums ----------------------------------
__global__ void ks1_bsum(int N) {
    int b = blockIdx.x, t = threadIdx.x, n = b * 1024 + t;
    int v = (n < N) ? g_deg[n] : 0;
    int l = t & 31, w = t >> 5;
    #pragma unroll
    for (int o = 16; o; o >>= 1) v += __shfl_down_sync(0xffffffffu, v, o);
    __shared__ int ws[32];
    if (l == 0) ws[w] = v;
    __syncthreads();
    if (w == 0) {
        int s = ws[l];
        #pragma unroll
        for (int o = 16; o; o >>= 1) s += __shfl_down_sync(0xffffffffu, s, o);
        if (l == 0) g_bsum[b] = s;
    }
}

// ---------------- KS2: exclusive scan of block sums (<=128 values) ------------
__global__ void ks2_bscan(int nb) {
    int t = threadIdx.x;  // blockDim = 128
    __shared__ int sh[128];
    int v = (t < nb) ? g_bsum[t] : 0;
    sh[t] = v;
    __syncthreads();
    for (int o = 1; o < 128; o <<= 1) {
        int u = (t >= o) ? sh[t - o] : 0;
        __syncthreads();
        sh[t] += u;
        __syncthreads();
    }
    if (t < nb) g_boff[t] = sh[t] - v;
}

// ---------------- KS3: per-node exclusive offsets -----------------------------
__global__ void ks3_scan(int N) {
    int b = blockIdx.x, t = threadIdx.x, n = b * 1024 + t;
    int l = t & 31, w = t >> 5;
    int v = (n < N) ? g_deg[n] : 0;
    int s = v;
    #pragma unroll
    for (int o = 1; o < 32; o <<= 1) {
        int u = __shfl_up_sync(0xffffffffu, s, o);
        if (l >= o) s += u;
    }
    __shared__ int ws[32];
    if (l == 31) ws[w] = s;
    __syncthreads();
    if (w == 0) {
        int x2 = ws[l];
        #pragma unroll
        for (int o = 1; o < 32; o <<= 1) {
            int u = __shfl_up_sync(0xffffffffu, x2, o);
            if (l >= o) x2 += u;
        }
        ws[l] = x2;
    }
    __syncthreads();
    int excl = s - v + (w ? ws[w - 1] : 0) + g_boff[b];
    if (n < N) { g_off[n] = excl; g_wr[n] = excl; }
}

// ---------------- KSC: scatter srcs into CSR ----------------------------------
__global__ void kscat(int E) {
    int e = blockIdx.x * blockDim.x + threadIdx.x;
    if (e >= E) return;
    int d = g_dst[e];
    int pos = atomicAdd(&g_wr[d], 1);
    g_csr[pos] = g_src[e];
}

// ---------------- K0: p_src/p_dst = W1_h @ att --------------------------------
__global__ void k0_proj(const float* __restrict__ W1,
                        const float* __restrict__ att_s,
                        const float* __restrict__ att_d) {
    int t = threadIdx.x;
    if (t >= 48) return;
    int which = t / 24, r = t % 24, h = r / 6, i = r % 6;
    const float* att = which ? att_d : att_s;
    float s = 0.f;
    #pragma unroll 8
    for (int c = 0; c < 64; c++)
        s += W1[i * 256 + h * 64 + c] * att[h * 64 + c];
    g_p[which * 24 + h * 6 + i] = s;
}

// ---------------- K1: node logits layer 1 -------------------------------------
__global__ void k1_logits1(const float* __restrict__ x, int N) {
    int n = blockIdx.x * blockDim.x + threadIdx.x;
    if (n >= N) return;
    float xv[6];
    #pragma unroll
    for (int i = 0; i < 6; i++) xv[i] = x[n * 6 + i];
    #pragma unroll
    for (int h = 0; h < 4; h++) {
        float as = 0.f, ad = 0.f;
        #pragma unroll
        for (int i = 0; i < 6; i++) {
            as += xv[i] * g_p[h * 6 + i];
            ad += xv[i] * g_p[24 + h * 6 + i];
        }
        g_as1[n * 4 + h] = as;
        g_ad1[n * 4 + h] = ad;
    }
}

// ---------------- K4: layer-1 CSR aggregation (thread per dst, all 4 heads) ---
// exp without max-shift: mathematically identical softmax, values bounded.
__global__ void k4_csr(const float* __restrict__ x, int N) {
    int d = blockIdx.x * blockDim.x + threadIdx.x;
    if (d >= N) return;
    float4 ad = *(const float4*)&g_ad1[d * 4];
    int off = g_off[d], deg = g_deg[d];
    float A[4][6], den[4];
    {   // self loop
        float4 av = *(const float4*)&g_as1[d * 4];
        float eh[4] = { __expf(lrelu(av.x + ad.x)), __expf(lrelu(av.y + ad.y)),
                        __expf(lrelu(av.z + ad.z)), __expf(lrelu(av.w + ad.w)) };
        const float2* xp = (const float2*)(x + (size_t)d * 6);
        float2 x0 = xp[0], x1 = xp[1], x2 = xp[2];
        float xs[6] = { x0.x, x0.y, x1.x, x1.y, x2.x, x2.y };
        #pragma unroll
        for (int h = 0; h < 4; h++) {
            den[h] = eh[h];
            #pragma unroll
            for (int i = 0; i < 6; i++) A[h][i] = eh[h] * xs[i];
        }
    }
    for (int i = 0; i < deg; i++) {
        int s = g_csr[off + i];
        float4 av = *(const float4*)&g_as1[s * 4];
        float eh[4] = { __expf(lrelu(av.x + ad.x)), __expf(lrelu(av.y + ad.y)),
                        __expf(lrelu(av.z + ad.z)), __expf(lrelu(av.w + ad.w)) };
        const float2* xp = (const float2*)(x + (size_t)s * 6);
        float2 x0 = xp[0], x1 = xp[1], x2 = xp[2];
        float xs[6] = { x0.x, x0.y, x1.x, x1.y, x2.x, x2.y };
        #pragma unroll
        for (int h = 0; h < 4; h++) {
            den[h] += eh[h];
            #pragma unroll
            for (int ii = 0; ii < 6; ii++) A[h][ii] += eh[h] * xs[ii];
        }
    }
    float* o = &g_acc1[d * 32];
    #pragma unroll
    for (int h = 0; h < 4; h++) {
        float4 lo = make_float4(A[h][0], A[h][1], A[h][2], A[h][3]);
        float4 hi = make_float4(A[h][4], A[h][5], den[h], 0.f);
        *(float4*)&o[h * 8]     = lo;
        *(float4*)&o[h * 8 + 4] = hi;
    }
}

// ---------------- K6F: fused  h2 = elu((acc@W1)/den + b1) @ W2 ----------------
// 32 nodes per 256-thread block. h1 tile lives only in shared memory.
__global__ void __launch_bounds__(256) k6_fused(
        const float* __restrict__ W1, const float* __restrict__ b1,
        const float* __restrict__ W2, int N) {
    __shared__ __align__(16) float sh[256 * 36];   // [k][node], pad 36
    __shared__ float sW1[1536];
    __shared__ float sb1[256];
    int t = threadIdx.x;
    int base = blockIdx.x * 32;
    for (int i = t; i < 1536; i += 256) sW1[i] = W1[i];
    sb1[t] = b1[t];
    __syncthreads();

    // ---- phase 1: build h1 tile in shared ----
    {
        int node = t & 31;           // warp-contiguous nodes -> conflict-free STS
        int jb   = t >> 5;           // 0..7
        int n = base + node; if (n >= N) n = N - 1;
        const float* accp = &g_acc1[n * 32];
        #pragma unroll
        for (int h = 0; h < 4; h++) {
            float4 lo = *(const float4*)&accp[h * 8];
            float4 hi = *(const float4*)&accp[h * 8 + 4];
            float inv = 1.f / fmaxf(hi.z, 1e-16f);
            #pragma unroll
            for (int m = 0; m < 8; m++) {
                int j = h * 64 + jb + m * 8;
                float v = lo.x * sW1[j] + lo.y * sW1[256 + j] + lo.z * sW1[512 + j]
                        + lo.w * sW1[768 + j] + hi.x * sW1[1024 + j] + hi.y * sW1[1280 + j];
                v = v * inv + sb1[j];
                sh[j * 36 + node] = eluf(v);
            }
        }
    }
    __syncthreads();

    // ---- phase 2: GEMM tile @ W2 (8 nodes x 1 col per thread) ----
    {
        int j = t & 63, ng = t >> 6;     // warp: same ng -> LDS broadcast
        float a0 = 0.f, a1 = 0.f, a2 = 0.f, a3 = 0.f;
        float a4 = 0.f, a5 = 0.f, a6 = 0.f, a7 = 0.f;
        const float* wp = W2 + j;
        #pragma unroll 4
        for (int k = 0; k < 256; k++) {
            float4 p = *(const float4*)&sh[k * 36 + ng * 8];
            float4 q = *(const float4*)&sh[k * 36 + ng * 8 + 4];
            float w = __ldg(&wp[k * 64]);
            a0 += p.x * w; a1 += p.y * w; a2 += p.z * w; a3 += p.w * w;
            a4 += q.x * w; a5 += q.y * w; a6 += q.z * w; a7 += q.w * w;
        }
        int n0 = base + ng * 8;
        float r[8] = { a0, a1, a2, a3, a4, a5, a6, a7 };
        #pragma unroll
        for (int m = 0; m < 8; m++)
            if (n0 + m < N) g_h2[(n0 + m) * 64 + j] = r[m];
    }
}

// ---------------- K6b: layer-2 logits (warp per node) -------------------------
__global__ void k6b_logits2(const float* __restrict__ att_s,
                            const float* __restrict__ att_d, int N) {
    int gt = blockIdx.x * blockDim.x + threadIdx.x;
    int n = gt >> 5, l = gt & 31;
    if (n >= N) return;
    float h0 = g_h2[n * 64 + l], h1v = g_h2[n * 64 + l + 32];
    float s = h0 * att_s[l] + h1v * att_s[l + 32];
    float d = h0 * att_d[l] + h1v * att_d[l + 32];
    #pragma unroll
    for (int o = 16; o; o >>= 1) {
        s += __shfl_down_sync(0xffffffffu, s, o);
        d += __shfl_down_sync(0xffffffffu, d, o);
    }
    if (l == 0) { g_as2[n] = s; g_ad2[n] = d; }
}

// ---------------- K9: layer-2 CSR aggregation, fully fused --------------------
__global__ void k9_csr(const float* __restrict__ b2, int N) {
    int gt = blockIdx.x * blockDim.x + threadIdx.x;
    int d = gt >> 5, l = gt & 31;
    if (d >= N) return;
    float add = g_ad2[d];
    int off = g_off[d], deg = g_deg[d];
    float eeS = __expf(lrelu(g_as2[d] + add));
    float2 hd = *(const float2*)&g_h2[d * 64 + l * 2];
    float ax = eeS * hd.x, ay = eeS * hd.y, den = eeS;
    int i = 0;
    for (; i + 4 <= deg; i += 4) {
        int s0 = g_csr[off + i],     s1 = g_csr[off + i + 1];
        int s2 = g_csr[off + i + 2], s3 = g_csr[off + i + 3];
        float e0 = __expf(lrelu(g_as2[s0] + add));
        float e1 = __expf(lrelu(g_as2[s1] + add));
        float e2 = __expf(lrelu(g_as2[s2] + add));
        float e3 = __expf(lrelu(g_as2[s3] + add));
        float2 h0 = *(const float2*)&g_h2[s0 * 64 + l * 2];
        float2 h1 = *(const float2*)&g_h2[s1 * 64 + l * 2];
        float2 h2v = *(const float2*)&g_h2[s2 * 64 + l * 2];
        float2 h3 = *(const float2*)&g_h2[s3 * 64 + l * 2];
        ax += e0 * h0.x + e1 * h1.x + e2 * h2v.x + e3 * h3.x;
        ay += e0 * h0.y + e1 * h1.y + e2 * h2v.y + e3 * h3.y;
        den += e0 + e1 + e2 + e3;
    }
    for (; i < deg; i++) {
        int s0 = g_csr[off + i];
        float e0 = __expf(lrelu(g_as2[s0] + add));
        float2 h0 = *(const float2*)&g_h2[s0 * 64 + l * 2];
        ax += e0 * h0.x; ay += e0 * h0.y; den += e0;
    }
    float inv = 1.f / fmaxf(den, 1e-16f);
    float v0 = ax * inv + b2[l * 2];
    float v1 = ay * inv + b2[l * 2 + 1];
    *(float2*)&g_hf[d * 64 + l * 2] = make_float2(eluf(v0), eluf(v1));
}

// ---------------- KCA/KCB/KCC: multi-block stable drone compaction ------------
__global__ void kca_count(const float* __restrict__ x, int N) {
    int b = blockIdx.x, t = threadIdx.x, n = b * 1024 + t;
    int l = t & 31, w = t >> 5;
    int f = (n < N) && (x[n * 6 + 5] == 1.0f);
    unsigned m = __ballot_sync(0xffffffffu, f);
    __shared__ int ws[32];
    if (l == 0) ws[w] = __popc(m);
    __syncthreads();
    if (w == 0) {
        int s = ws[l];
        #pragma unroll
        for (int o = 16; o; o >>= 1) s += __shfl_down_sync(0xffffffffu, s, o);
        if (l == 0) g_dsum[b] = s;
    }
}
__global__ void kcb_scan(int nb) {
    int t = threadIdx.x;  // 128
    __shared__ int sh[128];
    int v = (t < nb) ? g_dsum[t] : 0;
    sh[t] = v;
    __syncthreads();
    for (int o = 1; o < 128; o <<= 1) {
        int u = (t >= o) ? sh[t - o] : 0;
        __syncthreads();
        sh[t] += u;
        __syncthreads();
    }
    if (t < nb) g_dboff[t] = sh[t] - v;
}
__global__ void kcc_scatter(const float* __restrict__ x, int N, int nd) {
    int b = blockIdx.x, t = threadIdx.x, n = b * 1024 + t;
    int l = t & 31, w = t >> 5;
    int f = (n < N) && (x[n * 6 + 5] == 1.0f);
    unsigned m = __ballot_sync(0xffffffffu, f);
    int wpre = __popc(m & ((1u << l) - 1u));
    __shared__ int ws[32];
    if (l == 0) ws[w] = __popc(m);
    __syncthreads();
    if (w == 0) {
        int v = ws[l];
        #pragma unroll
        for (int o = 1; o < 32; o <<= 1) {
            int u = __shfl_up_sync(0xffffffffu, v, o);
            if (l >= o) v += u;
        }
        ws[l] = v;
    }
    __syncthreads();
    int base = g_dboff[b] + (w ? ws[w - 1] : 0);
    if (f) {
        int pos = base + wpre;
        if (pos < nd) g_didx[pos] = n;
    }
}

// ---------------- K12: drone MLP head -----------------------------------------
__global__ void k12_mlp(const float* __restrict__ fc1w, const float* __restrict__ fc1b,
                        const float* __restrict__ fc2w, const float* __restrict__ fc2b,
                        float* __restrict__ out, int nd) {
    __shared__ float sh[64];
    __shared__ float sz[64];
    int b = blockIdx.x;
    if (b >= nd) return;
    int n = g_didx[b];
    int j = threadIdx.x;
    sh[j] = g_hf[n * 64 + j];
    __syncthreads();
    float v = fc1b[j];
    #pragma unroll 8
    for (int k = 0; k < 64; k++) v += sh[k] * fc1w[k * 64 + j];
    sz[j] = fmaxf(v, 0.f);
    __syncthreads();
    if (j < 2) {
        float o = fc2b[j];
        #pragma unroll 8
        for (int k = 0; k < 64; k++) o += sz[k] * fc2w[k * 2 + j];
        out[b * 2 + j] = 2.f * tanhf(o);
    }
}

// ---------------- launch ------------------------------------------------------
static inline int cdiv(long long a, int b) { return (int)((a + b - 1) / b); }

extern "C" void kernel_launch(void* const* d_in, const int* in_sizes, int n_in,
                              void* d_out, int out_size) {
    // ---- size-based input identification (element counts) ----
    const void* p_ei = nullptr; const float* x = nullptr;
    const float *W1 = 0, *W2 = 0, *fc1w = 0, *fc2w = 0, *fc2b = 0;
    const float* s256[3] = {0, 0, 0}; int n256 = 0;
    const float* s64g[4] = {0, 0, 0, 0}; int n64 = 0;
    long long sz_big1 = 0, sz_big2 = 0;
    const void *p_big1 = 0, *p_big2 = 0;

    for (int i = 0; i < n_in; i++) {
        long long s = in_sizes[i];
        const void* p = d_in[i];
        if (s > 20000) {
            if (s > sz_big1) { sz_big2 = sz_big1; p_big2 = p_big1; sz_big1 = s; p_big1 = p; }
            else if (s > sz_big2) { sz_big2 = s; p_big2 = p; }
        } else if (s == 16384) W2 = (const float*)p;
        else if (s == 4096) fc1w = (const float*)p;
        else if (s == 1536) W1 = (const float*)p;
        else if (s == 128)  fc2w = (const float*)p;
        else if (s == 2)    fc2b = (const float*)p;
        else if (s == 256) { if (n256 < 3) s256[n256++] = (const float*)p; }
        else if (s == 64)  { if (n64 < 4)  s64g[n64++] = (const float*)p; }
    }
    p_ei = p_big1;
    x    = (const float*)p_big2;

    bool insertion = (n_in >= 2) && ((long long)in_sizes[1] == sz_big1);
    const float* a_s1 = insertion ? s256[0] : s256[1];
    const float* a_d1 = insertion ? s256[1] : s256[0];
    const float* b1   = s256[2];
    const float* a_s2 = insertion ? s64g[0] : s64g[1];
    const float* a_d2 = insertion ? s64g[1] : s64g[0];
    const float* b2   = s64g[2];
    const float* fc1b = s64g[3];
    float* out = (float*)d_out;

    int N  = (int)(sz_big2 / 6);
    int E  = (int)(sz_big1 / 2);
    int nd = out_size / 2;
    if (N > MAXN) N = MAXN;
    if (E > MAXE) E = MAXE;
    int nb = cdiv(N, 1024);            // <= 98

    kd_detect  <<<1, 32>>>((const long long*)p_ei, N);
    kz_zero    <<<nb, 1024>>>(N);
    kc_cvt     <<<cdiv(E, 256), 256>>>(p_ei, E, N);
    ks1_bsum   <<<nb, 1024>>>(N);
    ks2_bscan  <<<1, 128>>>(nb);
    ks3_scan   <<<nb, 1024>>>(N);
    kscat      <<<cdiv(E, 256), 256>>>(E);
    k0_proj    <<<1, 64>>>(W1, a_s1, a_d1);
    k1_logits1 <<<cdiv(N, 256), 256>>>(x, N);
    k4_csr     <<<cdiv(N, 256), 256>>>(x, N);
    k6_fused   <<<cdiv(N, 32), 256>>>(W1, b1, W2, N);
    k6b_logits2<<<cdiv((long long)N * 32, 256), 256>>>(a_s2, a_d2, N);
    k9_csr     <<<cdiv((long long)N * 32, 256), 256>>>(b2, N);
    kca_count  <<<nb, 1024>>>(x, N);
    kcb_scan   <<<1, 128>>>(nb);
    kcc_scatter<<<nb, 1024>>>(x, N, nd);
    k12_mlp    <<<nd, 64>>>(fc1w, fc1b, fc2w, fc2b, out, nd);
}

// round 15
// speedup vs baseline: 1.9072x; 1.0117x over previous
#include <cuda_runtime.h>
#include <cstdint>

#define MAXN 100000
#define MAXE 2000000
#define MAXNB 128   // max 1024-blocks covering N

// ---------------- scratch (device globals) ------------------------------------
__device__ __align__(16) float g_p[48];                    // p_src[4][6] | p_dst[4][6]
__device__ __align__(16) float g_as1[MAXN * 4];
__device__ __align__(16) float g_ad1[MAXN * 4];
__device__ __align__(16) float g_acc1[MAXN * 32];          // [n][h][8]: sum(e*x0..5), den, pad
__device__ __align__(16) float g_h2[MAXN * 64];            // elu(out1) @ W2
__device__ __align__(16) float g_as2[MAXN];
__device__ __align__(16) float g_ad2[MAXN];
__device__ __align__(16) float g_hf[MAXN * 64];            // layer-2 output (post elu)
__device__ __align__(16) int   g_didx[MAXN];
__device__ __align__(16) int   g_src[MAXE];
__device__ __align__(16) int   g_dst[MAXE];
__device__ __align__(16) int   g_csr[MAXE];                // src ids grouped by dst
__device__ __align__(16) int   g_deg[MAXN];
__device__ __align__(16) int   g_off[MAXN];
__device__ __align__(16) int   g_wr[MAXN];
__device__ int g_bsum[MAXNB];
__device__ int g_boff[MAXNB];
__device__ int g_dsum[MAXNB];
__device__ int g_dboff[MAXNB];
__device__ int g_is64;

// ---------------- helpers ----------------------------------------------------
__device__ __forceinline__ float lrelu(float v) { return v > 0.f ? v : 0.2f * v; }
__device__ __forceinline__ float eluf(float v)  { return v > 0.f ? v : expm1f(v); }
__device__ __forceinline__ void ffma2(unsigned long long& acc,
                                      unsigned long long a, unsigned long long b) {
    asm("fma.rn.f32x2 %0, %1, %2, %0;" : "+l"(acc) : "l"(a), "l"(b));
}

// ---------------- KZ: zero deg + didx, + dtype probe (block 0) ----------------
__global__ void kz_zero(const long long* __restrict__ ei, int N) {
    int n = blockIdx.x * blockDim.x + threadIdx.x;
    if (n < N) { g_deg[n] = 0; g_didx[n] = 0; }
    if (blockIdx.x == 0 && threadIdx.x == 0) {
        bool ok = true;
        #pragma unroll
        for (int i = 0; i < 16; i++) {
            long long v = ei[i];
            if (v < 0 || v >= (long long)N) { ok = false; break; }
        }
        g_is64 = ok ? 1 : 0;
    }
}

// ---------------- KC: decode edge list + histogram ----------------------------
__global__ void kc_cvt(const void* __restrict__ ei, int E, int N) {
    int e = blockIdx.x * blockDim.x + threadIdx.x;
    if (e >= E) return;
    int s, d;
    if (g_is64) {
        const long long* p = (const long long*)ei;
        s = (int)p[e]; d = (int)p[e + E];
    } else {
        const int* p = (const int*)ei;
        s = p[e]; d = p[e + E];
    }
    if ((unsigned)s >= (unsigned)N) s = 0;
    if ((unsigned)d >= (unsigned)N) d = 0;
    g_src[e] = s;
    g_dst[e] = d;
    atomicAdd(&g_deg[d], 1);
}

// ---------------- KS1: per-block degree sums ----------------------------------
__global__ void ks1_bsum(int N) {
    int b = blockIdx.x, t = threadIdx.x, n = b * 1024 + t;
    int v = (n < N) ? g_deg[n] : 0;
    int l = t & 31, w = t >> 5;
    #pragma unroll
    for (int o = 16; o; o >>= 1) v += __shfl_down_sync(0xffffffffu, v, o);
    __shared__ int ws[32];
    if (l == 0) ws[w] = v;
    __syncthreads();
    if (w == 0) {
        int s = ws[l];
        #pragma unroll
        for (int o = 16; o; o >>= 1) s += __shfl_down_sync(0xffffffffu, s, o);
        if (l == 0) g_bsum[b] = s;
    }
}

// ---------------- KS2: exclusive scan of block sums (<=128 values) ------------
__global__ void ks2_bscan(int nb) {
    int t = threadIdx.x;  // blockDim = 128
    __shared__ int sh[128];
    int v = (t < nb) ? g_bsum[t] : 0;
    sh[t] = v;
    __syncthreads();
    for (int o = 1; o < 128; o <<= 1) {
        int u = (t >= o) ? sh[t - o] : 0;
        __syncthreads();
        sh[t] += u;
        __syncthreads();
    }
    if (t < nb) g_boff[t] = sh[t] - v;
}

// ---------------- KS3: per-node exclusive offsets -----------------------------
__global__ void ks3_scan(int N) {
    int b = blockIdx.x, t = threadIdx.x, n = b * 1024 + t;
    int l = t & 31, w = t >> 5;
    int v = (n < N) ? g_deg[n] : 0;
    int s = v;
    #pragma unroll
    for (int o = 1; o < 32; o <<= 1) {
        int u = __shfl_up_sync(0xffffffffu, s, o);
        if (l >= o) s += u;
    }
    __shared__ int ws[32];
    if (l == 31) ws[w] = s;
    __syncthreads();
    if (w == 0) {
        int x2 = ws[l];
        #pragma unroll
        for (int o = 1; o < 32; o <<= 1) {
            int u = __shfl_up_sync(0xffffffffu, x2, o);
            if (l >= o) x2 += u;
        }
        ws[l] = x2;
    }
    __syncthreads();
    int excl = s - v + (w ? ws[w - 1] : 0) + g_boff[b];
    if (n < N) { g_off[n] = excl; g_wr[n] = excl; }
}

// ---------------- KSC: scatter srcs into CSR ----------------------------------
__global__ void kscat(int E) {
    int e = blockIdx.x * blockDim.x + threadIdx.x;
    if (e >= E) return;
    int d = g_dst[e];
    int pos = atomicAdd(&g_wr[d], 1);
    g_csr[pos] = g_src[e];
}

// ---------------- K0: p_src/p_dst = W1_h @ att --------------------------------
__global__ void k0_proj(const float* __restrict__ W1,
                        const float* __restrict__ att_s,
                        const float* __restrict__ att_d) {
    int t = threadIdx.x;
    if (t >= 48) return;
    int which = t / 24, r = t % 24, h = r / 6, i = r % 6;
    const float* att = which ? att_d : att_s;
    float s = 0.f;
    #pragma unroll 8
    for (int c = 0; c < 64; c++)
        s += W1[i * 256 + h * 64 + c] * att[h * 64 + c];
    g_p[which * 24 + h * 6 + i] = s;
}

// ---------------- K1: node logits layer 1 -------------------------------------
__global__ void k1_logits1(const float* __restrict__ x, int N) {
    int n = blockIdx.x * blockDim.x + threadIdx.x;
    if (n >= N) return;
    float xv[6];
    #pragma unroll
    for (int i = 0; i < 6; i++) xv[i] = x[n * 6 + i];
    #pragma unroll
    for (int h = 0; h < 4; h++) {
        float as = 0.f, ad = 0.f;
        #pragma unroll
        for (int i = 0; i < 6; i++) {
            as += xv[i] * g_p[h * 6 + i];
            ad += xv[i] * g_p[24 + h * 6 + i];
        }
        g_as1[n * 4 + h] = as;
        g_ad1[n * 4 + h] = ad;
    }
}

// ---------------- K4: layer-1 CSR aggregation (thread per dst, all 4 heads) ---
// exp without max-shift: mathematically identical softmax, values bounded.
__global__ void k4_csr(const float* __restrict__ x, int N) {
    int d = blockIdx.x * blockDim.x + threadIdx.x;
    if (d >= N) return;
    float4 ad = *(const float4*)&g_ad1[d * 4];
    int off = g_off[d], deg = g_deg[d];
    float A[4][6], den[4];
    {   // self loop
        float4 av = *(const float4*)&g_as1[d * 4];
        float eh[4] = { __expf(lrelu(av.x + ad.x)), __expf(lrelu(av.y + ad.y)),
                        __expf(lrelu(av.z + ad.z)), __expf(lrelu(av.w + ad.w)) };
        const float2* xp = (const float2*)(x + (size_t)d * 6);
        float2 x0 = xp[0], x1 = xp[1], x2 = xp[2];
        float xs[6] = { x0.x, x0.y, x1.x, x1.y, x2.x, x2.y };
        #pragma unroll
        for (int h = 0; h < 4; h++) {
            den[h] = eh[h];
            #pragma unroll
            for (int i = 0; i < 6; i++) A[h][i] = eh[h] * xs[i];
        }
    }
    for (int i = 0; i < deg; i++) {
        int s = g_csr[off + i];
        float4 av = *(const float4*)&g_as1[s * 4];
        float eh[4] = { __expf(lrelu(av.x + ad.x)), __expf(lrelu(av.y + ad.y)),
                        __expf(lrelu(av.z + ad.z)), __expf(lrelu(av.w + ad.w)) };
        const float2* xp = (const float2*)(x + (size_t)s * 6);
        float2 x0 = xp[0], x1 = xp[1], x2 = xp[2];
        float xs[6] = { x0.x, x0.y, x1.x, x1.y, x2.x, x2.y };
        #pragma unroll
        for (int h = 0; h < 4; h++) {
            den[h] += eh[h];
            #pragma unroll
            for (int ii = 0; ii < 6; ii++) A[h][ii] += eh[h] * xs[ii];
        }
    }
    float* o = &g_acc1[d * 32];
    #pragma unroll
    for (int h = 0; h < 4; h++) {
        float4 lo = make_float4(A[h][0], A[h][1], A[h][2], A[h][3]);
        float4 hi = make_float4(A[h][4], A[h][5], den[h], 0.f);
        *(float4*)&o[h * 8]     = lo;
        *(float4*)&o[h * 8 + 4] = hi;
    }
}

// ---------------- K6F: fused  h2 = elu((acc@W1)/den + b1) @ W2 ----------------
// 32 nodes per 256-thread block. h1 tile lives only in shared memory.
// Phase 2 uses packed fma.rn.f32x2 (FFMA2): 2x fp32 FMA throughput vs scalar
// FFMA (rt_SMSP=2) -- ptxas never emits it from C++, PTX-only path.
__global__ void __launch_bounds__(256) k6_fused(
        const float* __restrict__ W1, const float* __restrict__ b1,
        const float* __restrict__ W2, int N) {
    __shared__ __align__(16) float sh[256 * 36];   // [k][node], pad 36
    __shared__ float sW1[1536];
    __shared__ float sb1[256];
    int t = threadIdx.x;
    int base = blockIdx.x * 32;
    for (int i = t; i < 1536; i += 256) sW1[i] = W1[i];
    sb1[t] = b1[t];
    __syncthreads();

    // ---- phase 1: build h1 tile in shared ----
    {
        int node = t & 31;           // warp-contiguous nodes -> conflict-free STS
        int jb   = t >> 5;           // 0..7
        int n = base + node; if (n >= N) n = N - 1;
        const float* accp = &g_acc1[n * 32];
        #pragma unroll
        for (int h = 0; h < 4; h++) {
            float4 lo = *(const float4*)&accp[h * 8];
            float4 hi = *(const float4*)&accp[h * 8 + 4];
            float inv = 1.f / fmaxf(hi.z, 1e-16f);
            #pragma unroll
            for (int m = 0; m < 8; m++) {
                int j = h * 64 + jb + m * 8;
                float v = lo.x * sW1[j] + lo.y * sW1[256 + j] + lo.z * sW1[512 + j]
                        + lo.w * sW1[768 + j] + hi.x * sW1[1024 + j] + hi.y * sW1[1280 + j];
                v = v * inv + sb1[j];
                sh[j * 36 + node] = eluf(v);
            }
        }
    }
    __syncthreads();

    // ---- phase 2: GEMM tile @ W2, packed f32x2 (8 nodes x 1 col per thread) --
    {
        int j = t & 63, ng = t >> 6;     // warp: same ng -> LDS broadcast
        unsigned long long A0 = 0ull, A1 = 0ull, A2 = 0ull, A3 = 0ull;
        const float* wp = W2 + j;
        #pragma unroll 4
        for (int k = 0; k < 256; k++) {
            ulonglong2 P = *(const ulonglong2*)&sh[k * 36 + ng * 8];
            ulonglong2 Q = *(const ulonglong2*)&sh[k * 36 + ng * 8 + 4];
            unsigned wu = __float_as_uint(__ldg(&wp[k * 64]));
            unsigned long long ww;
            asm("mov.b64 %0, {%1, %1};" : "=l"(ww) : "r"(wu));
            ffma2(A0, P.x, ww);
            ffma2(A1, P.y, ww);
            ffma2(A2, Q.x, ww);
            ffma2(A3, Q.y, ww);
        }
        int n0 = base + ng * 8;
        unsigned long long Ar[4] = { A0, A1, A2, A3 };
        #pragma unroll
        for (int m2 = 0; m2 < 4; m2++) {
            unsigned lo32, hi32;
            asm("mov.b64 {%0, %1}, %2;" : "=r"(lo32), "=r"(hi32) : "l"(Ar[m2]));
            int na = n0 + m2 * 2, nb2 = na + 1;
            if (na  < N) g_h2[na  * 64 + j] = __uint_as_float(lo32);
            if (nb2 < N) g_h2[nb2 * 64 + j] = __uint_as_float(hi32);
        }
    }
}

// ---------------- K6b: layer-2 logits (warp per node) -------------------------
__global__ void k6b_logits2(const float* __restrict__ att_s,
                            const float* __restrict__ att_d, int N) {
    int gt = blockIdx.x * blockDim.x + threadIdx.x;
    int n = gt >> 5, l = gt & 31;
    if (n >= N) return;
    float h0 = g_h2[n * 64 + l], h1v = g_h2[n * 64 + l + 32];
    float s = h0 * att_s[l] + h1v * att_s[l + 32];
    float d = h0 * att_d[l] + h1v * att_d[l + 32];
    #pragma unroll
    for (int o = 16; o; o >>= 1) {
        s += __shfl_down_sync(0xffffffffu, s, o);
        d += __shfl_down_sync(0xffffffffu, d, o);
    }
    if (l == 0) { g_as2[n] = s; g_ad2[n] = d; }
}

// ---------------- K9: layer-2 CSR aggregation, fully fused --------------------
__global__ void k9_csr(const float* __restrict__ b2, int N) {
    int gt = blockIdx.x * blockDim.x + threadIdx.x;
    int d = gt >> 5, l = gt & 31;
    if (d >= N) return;
    float add = g_ad2[d];
    int off = g_off[d], deg = g_deg[d];
    float eeS = __expf(lrelu(g_as2[d] + add));
    float2 hd = *(const float2*)&g_h2[d * 64 + l * 2];
    float ax = eeS * hd.x, ay = eeS * hd.y, den = eeS;
    int i = 0;
    for (; i + 4 <= deg; i += 4) {
        int s0 = g_csr[off + i],     s1 = g_csr[off + i + 1];
        int s2 = g_csr[off + i + 2], s3 = g_csr[off + i + 3];
        float e0 = __expf(lrelu(g_as2[s0] + add));
        float e1 = __expf(lrelu(g_as2[s1] + add));
        float e2 = __expf(lrelu(g_as2[s2] + add));
        float e3 = __expf(lrelu(g_as2[s3] + add));
        float2 h0 = *(const float2*)&g_h2[s0 * 64 + l * 2];
        float2 h1 = *(const float2*)&g_h2[s1 * 64 + l * 2];
        float2 h2v = *(const float2*)&g_h2[s2 * 64 + l * 2];
        float2 h3 = *(const float2*)&g_h2[s3 * 64 + l * 2];
        ax += e0 * h0.x + e1 * h1.x + e2 * h2v.x + e3 * h3.x;
        ay += e0 * h0.y + e1 * h1.y + e2 * h2v.y + e3 * h3.y;
        den += e0 + e1 + e2 + e3;
    }
    for (; i < deg; i++) {
        int s0 = g_csr[off + i];
        float e0 = __expf(lrelu(g_as2[s0] + add));
        float2 h0 = *(const float2*)&g_h2[s0 * 64 + l * 2];
        ax += e0 * h0.x; ay += e0 * h0.y; den += e0;
    }
    float inv = 1.f / fmaxf(den, 1e-16f);
    float v0 = ax * inv + b2[l * 2];
    float v1 = ay * inv + b2[l * 2 + 1];
    *(float2*)&g_hf[d * 64 + l * 2] = make_float2(eluf(v0), eluf(v1));
}

// ---------------- KCA/KCB/KCC: multi-block stable drone compaction ------------
__global__ void kca_count(const float* __restrict__ x, int N) {
    int b = blockIdx.x, t = threadIdx.x, n = b * 1024 + t;
    int l = t & 31, w = t >> 5;
    int f = (n < N) && (x[n * 6 + 5] == 1.0f);
    unsigned m = __ballot_sync(0xffffffffu, f);
    __shared__ int ws[32];
    if (l == 0) ws[w] = __popc(m);
    __syncthreads();
    if (w == 0) {
        int s = ws[l];
        #pragma unroll
        for (int o = 16; o; o >>= 1) s += __shfl_down_sync(0xffffffffu, s, o);
        if (l == 0) g_dsum[b] = s;
    }
}
__global__ void kcb_scan(int nb) {
    int t = threadIdx.x;  // 128
    __shared__ int sh[128];
    int v = (t < nb) ? g_dsum[t] : 0;
    sh[t] = v;
    __syncthreads();
    for (int o = 1; o < 128; o <<= 1) {
        int u = (t >= o) ? sh[t - o] : 0;
        __syncthreads();
        sh[t] += u;
        __syncthreads();
    }
    if (t < nb) g_dboff[t] = sh[t] - v;
}
__global__ void kcc_scatter(const float* __restrict__ x, int N, int nd) {
    int b = blockIdx.x, t = threadIdx.x, n = b * 1024 + t;
    int l = t & 31, w = t >> 5;
    int f = (n < N) && (x[n * 6 + 5] == 1.0f);
    unsigned m = __ballot_sync(0xffffffffu, f);
    int wpre = __popc(m & ((1u << l) - 1u));
    __shared__ int ws[32];
    if (l == 0) ws[w] = __popc(m);
    __syncthreads();
    if (w == 0) {
        int v = ws[l];
        #pragma unroll
        for (int o = 1; o < 32; o <<= 1) {
            int u = __shfl_up_sync(0xffffffffu, v, o);
            if (l >= o) v += u;
        }
        ws[l] = v;
    }
    __syncthreads();
    int base = g_dboff[b] + (w ? ws[w - 1] : 0);
    if (f) {
        int pos = base + wpre;
        if (pos < nd) g_didx[pos] = n;
    }
}

// ---------------- K12: drone MLP head -----------------------------------------
__global__ void k12_mlp(const float* __restrict__ fc1w, const float* __restrict__ fc1b,
                        const float* __restrict__ fc2w, const float* __restrict__ fc2b,
                        float* __restrict__ out, int nd) {
    __shared__ float sh[64];
    __shared__ float sz[64];
    int b = blockIdx.x;
    if (b >= nd) return;
    int n = g_didx[b];
    int j = threadIdx.x;
    sh[j] = g_hf[n * 64 + j];
    __syncthreads();
    float v = fc1b[j];
    #pragma unroll 8
    for (int k = 0; k < 64; k++) v += sh[k] * fc1w[k * 64 + j];
    sz[j] = fmaxf(v, 0.f);
    __syncthreads();
    if (j < 2) {
        float o = fc2b[j];
        #pragma unroll 8
        for (int k = 0; k < 64; k++) o += sz[k] * fc2w[k * 2 + j];
        out[b * 2 + j] = 2.f * tanhf(o);
    }
}

// ---------------- launch ------------------------------------------------------
static inline int cdiv(long long a, int b) { return (int)((a + b - 1) / b); }

extern "C" void kernel_launch(void* const* d_in, const int* in_sizes, int n_in,
                              void* d_out, int out_size) {
    // ---- size-based input identification (element counts) ----
    const void* p_ei = nullptr; const float* x = nullptr;
    const float *W1 = 0, *W2 = 0, *fc1w = 0, *fc2w = 0, *fc2b = 0;
    const float* s256[3] = {0, 0, 0}; int n256 = 0;
    const float* s64g[4] = {0, 0, 0, 0}; int n64 = 0;
    long long sz_big1 = 0, sz_big2 = 0;
    const void *p_big1 = 0, *p_big2 = 0;

    for (int i = 0; i < n_in; i++) {
        long long s = in_sizes[i];
        const void* p = d_in[i];
        if (s > 20000) {
            if (s > sz_big1) { sz_big2 = sz_big1; p_big2 = p_big1; sz_big1 = s; p_big1 = p; }
            else if (s > sz_big2) { sz_big2 = s; p_big2 = p; }
        } else if (s == 16384) W2 = (const float*)p;
        else if (s == 4096) fc1w = (const float*)p;
        else if (s == 1536) W1 = (const float*)p;
        else if (s == 128)  fc2w = (const float*)p;
        else if (s == 2)    fc2b = (const float*)p;
        else if (s == 256) { if (n256 < 3) s256[n256++] = (const float*)p; }
        else if (s == 64)  { if (n64 < 4)  s64g[n64++] = (const float*)p; }
    }
    p_ei = p_big1;
    x    = (const float*)p_big2;

    bool insertion = (n_in >= 2) && ((long long)in_sizes[1] == sz_big1);
    const float* a_s1 = insertion ? s256[0] : s256[1];
    const float* a_d1 = insertion ? s256[1] : s256[0];
    const float* b1   = s256[2];
    const float* a_s2 = insertion ? s64g[0] : s64g[1];
    const float* a_d2 = insertion ? s64g[1] : s64g[0];
    const float* b2   = s64g[2];
    const float* fc1b = s64g[3];
    float* out = (float*)d_out;

    int N  = (int)(sz_big2 / 6);
    int E  = (int)(sz_big1 / 2);
    int nd = out_size / 2;
    if (N > MAXN) N = MAXN;
    if (E > MAXE) E = MAXE;
    int nb = cdiv(N, 1024);            // <= 98

    kz_zero    <<<nb, 1024>>>((const long long*)p_ei, N);
    kc_cvt     <<<cdiv(E, 256), 256>>>(p_ei, E, N);
    ks1_bsum   <<<nb, 1024>>>(N);
    ks2_bscan  <<<1, 128>>>(nb);
    ks3_scan   <<<nb, 1024>>>(N);
    kscat      <<<cdiv(E, 256), 256>>>(E);
    k0_proj    <<<1, 64>>>(W1, a_s1, a_d1);
    k1_logits1 <<<cdiv(N, 256), 256>>>(x, N);
    k4_csr     <<<cdiv(N, 256), 256>>>(x, N);
    k6_fused   <<<cdiv(N, 32), 256>>>(W1, b1, W2, N);
    k6b_logits2<<<cdiv((long long)N * 32, 256), 256>>>(a_s2, a_d2, N);
    k9_csr     <<<cdiv((long long)N * 32, 256), 256>>>(b2, N);
    kca_count  <<<nb, 1024>>>(x, N);
    kcb_scan   <<<1, 128>>>(nb);
    kcc_scatter<<<nb, 1024>>>(x, N, nd);
    k12_mlp    <<<nd, 64>>>(fc1w, fc1b, fc2w, fc2b, out, nd);
}